// round 16
// baseline (speedup 1.0000x reference)
#include <cuda_runtime.h>
#include <cuda_fp16.h>
#include <mma.h>
#include <cstdint>

using namespace nvcuda;

#define D   512
#define E   16
#define H1  128
#define H2  64
#define R   32
#define C1  (E * H1)   // 2048
#define C2  (E * H2)   // 1024
#define NMAX 65536

// ---------------- scratch (device globals: allocation-free) ----------------
__device__ __half g_x16[(size_t)NMAX * D];        // 64 MB
__device__ __half g_W1p[(size_t)D * C1];          // 2 MB   [d][e*128+j]
__device__ __half g_W2h[(size_t)E * H1 * H2];     // 256 KB [e][k][j]
__device__ __half g_Wg16[D * E];                  // 16 KB  [d][e] fp16
__device__ __half g_h1[(size_t)NMAX * C1];        // 256 MB
__device__ __half g_h2[(size_t)NMAX * C2];        // 128 MB
__device__ float  g_gate[(size_t)NMAX * E];       // 4 MB
__device__ float  g_sum1[C1], g_ssq1[C1];
__device__ float  g_sum2[C2], g_ssq2[C2];
__device__ float  g_v[C2];

// ---------------- cp.async helpers ----------------
__device__ __forceinline__ void cp_async16(void* smem, const void* gmem) {
    unsigned int s = (unsigned int)__cvta_generic_to_shared(smem);
    asm volatile("cp.async.cg.shared.global [%0], [%1], 16;\n" :: "r"(s), "l"(gmem));
}
__device__ __forceinline__ void cp_commit() {
    asm volatile("cp.async.commit_group;\n");
}
template <int NN>
__device__ __forceinline__ void cp_wait() {
    asm volatile("cp.async.wait_group %0;\n" :: "n"(NN));
}

// ---------------- 0: pack all weights + zero stats ----------------
__global__ void __launch_bounds__(256) pack_all(const float* __restrict__ W1,
                                                const float* __restrict__ W2,
                                                const float* __restrict__ W3,
                                                const float* __restrict__ Ws,
                                                const float* __restrict__ Wg) {
    int idx = blockIdx.x * 256 + threadIdx.x;   // grid 4096 -> 1048576
    if (idx < E * D * H1) {
        int j = idx & (H1 - 1);
        int d = (idx >> 7) & (D - 1);
        int e = idx >> 16;
        g_W1p[(size_t)d * C1 + e * H1 + j] = __float2half_rn(W1[idx]);
    }
    if (idx < E * H1 * H2) g_W2h[idx] = __float2half_rn(W2[idx]);
    if (idx < D * E) g_Wg16[idx] = __float2half_rn(Wg[idx]);
    if (idx < C2) {
        float v = 0.f;
#pragma unroll
        for (int r = 0; r < R; ++r) v = fmaf(W3[(size_t)idx * R + r], Ws[r], v);
        g_v[idx] = v;
        g_sum2[idx] = 0.f; g_ssq2[idx] = 0.f;
    }
    if (idx < C1) { g_sum1[idx] = 0.f; g_ssq1[idx] = 0.f; }
}

// ---------------- 1: fused convert x->fp16 + gating GEMM + LN + softmax ----------------
#define GG_WG   16384
#define GG_STG  18432
#define GG_SMEM (GG_WG + 2 * GG_STG)   // 53248

__global__ void __launch_bounds__(256) gate_convert(const float* __restrict__ x,
                                                    const float* __restrict__ bg,
                                                    const float* __restrict__ gamma_,
                                                    const float* __restrict__ beta_) {
    extern __shared__ char smg[];
    __half* Wgs = reinterpret_cast<__half*>(smg);
    const size_t m0 = (size_t)blockIdx.x * 128;
    const int tid = threadIdx.x;
    const int warp = tid >> 5;

#pragma unroll
    for (int i = 0; i < 4; ++i) {
        int c = tid + i * 256;
        cp_async16(Wgs + c * 8, g_Wg16 + c * 8);
    }
    cp_commit();

    float4 reg[8];
    auto preload = [&](int kt) {
#pragma unroll
        for (int i = 0; i < 8; ++i) {
            int c = tid + i * 256;
            int r = c >> 4, c4 = c & 15;
            reg[i] = *reinterpret_cast<const float4*>(
                x + (m0 + r) * D + kt * 64 + c4 * 4);
        }
    };
    auto store_stage = [&](int s, int kt) {
        __half* A = reinterpret_cast<__half*>(smg + GG_WG + s * GG_STG);
#pragma unroll
        for (int i = 0; i < 8; ++i) {
            int c = tid + i * 256;
            int r = c >> 4, c4 = c & 15;
            __half2 h0 = __floats2half2_rn(reg[i].x, reg[i].y);
            __half2 h1 = __floats2half2_rn(reg[i].z, reg[i].w);
            uint2 u = make_uint2(*reinterpret_cast<unsigned*>(&h0),
                                 *reinterpret_cast<unsigned*>(&h1));
            *reinterpret_cast<uint2*>(A + r * 72 + c4 * 4) = u;
            *reinterpret_cast<uint2*>(g_x16 + (m0 + r) * D + kt * 64 + c4 * 4) = u;
        }
    };

    wmma::fragment<wmma::accumulator, 16, 16, 16, float> acc;
    wmma::fill_fragment(acc, 0.0f);

    preload(0);
    for (int kt = 0; kt < 8; ++kt) {
        const int s = kt & 1;
        store_stage(s, kt);
        if (kt < 7) preload(kt + 1);
        if (kt == 0) cp_wait<0>();
        __syncthreads();

        const __half* A = reinterpret_cast<const __half*>(smg + GG_WG + s * GG_STG);
#pragma unroll
        for (int kk = 0; kk < 4; ++kk) {
            wmma::fragment<wmma::matrix_a, 16, 16, 16, __half, wmma::row_major> af;
            wmma::fragment<wmma::matrix_b, 16, 16, 16, __half, wmma::row_major> bf;
            wmma::load_matrix_sync(af, A + (warp * 16) * 72 + kk * 16, 72);
            wmma::load_matrix_sync(bf, Wgs + (kt * 64 + kk * 16) * E, E);
            wmma::mma_sync(acc, af, bf, acc);
        }
    }

    float* gsm = reinterpret_cast<float*>(smg + GG_WG);
    wmma::store_matrix_sync(gsm + warp * 16 * 20, acc, 20, wmma::mem_row_major);
    __syncthreads();

    if (tid < 128) {
        float g[E];
        float mu = 0.f;
#pragma unroll
        for (int e = 0; e < E; ++e) {
            g[e] = gsm[tid * 20 + e] + bg[e];
            mu += g[e];
        }
        mu *= (1.f / 16.f);
        float vv = 0.f;
#pragma unroll
        for (int e = 0; e < E; ++e) {
            g[e] -= mu;
            vv = fmaf(g[e], g[e], vv);
        }
        float rstd = rsqrtf(vv * (1.f / 16.f) + 1e-5f);
        float mx = -1e30f;
#pragma unroll
        for (int e = 0; e < E; ++e) {
            g[e] = g[e] * rstd * gamma_[e] + beta_[e];
            mx = fmaxf(mx, g[e]);
        }
        float es = 0.f;
#pragma unroll
        for (int e = 0; e < E; ++e) {
            g[e] = __expf(g[e] - mx);
            es += g[e];
        }
        float inv = 1.f / es;
        float4* gp = reinterpret_cast<float4*>(g_gate + (m0 + tid) * E);
#pragma unroll
        for (int q = 0; q < 4; ++q)
            gp[q] = make_float4(g[4 * q] * inv, g[4 * q + 1] * inv,
                                g[4 * q + 2] * inv, g[4 * q + 3] * inv);
    }
}

// ---------------- 2: GEMM1 h1 = x16 @ W1p (R9 mainloop, frozen at 450us) ----------------
#define G1_STAGE 35840
#define G1_SMEM  (3 * G1_STAGE)   // 107520

__global__ void __launch_bounds__(256) gemm1_kernel() {
    extern __shared__ char smbuf[];
    const int n0 = blockIdx.x * 128;
    const size_t m0 = (size_t)blockIdx.y * 128;
    const int tid = threadIdx.x;
    const int warp = tid >> 5;
    const int wm = warp & 3;    // 4 warps over M
    const int wn = warp >> 2;   // 2 warps over N

    wmma::fragment<wmma::accumulator, 16, 16, 16, float> acc[2][4];
#pragma unroll
    for (int i = 0; i < 2; ++i)
#pragma unroll
        for (int j = 0; j < 4; ++j) wmma::fill_fragment(acc[i][j], 0.0f);

    auto issue = [&](int kt, int s) {
        const int k0 = kt * 64;
        __half* A = reinterpret_cast<__half*>(smbuf + s * G1_STAGE);
        __half* B = A + 9216;   // 128*72 halves
#pragma unroll
        for (int i = 0; i < 4; ++i) {
            int c = tid + i * 256;            // 0..1023
            int r = c >> 3, off = (c & 7) * 8;
            cp_async16(A + r * 72 + off, g_x16 + (m0 + r) * D + k0 + off);
        }
#pragma unroll
        for (int i = 0; i < 4; ++i) {
            int c = tid + i * 256;
            int r = c >> 4, off = (c & 15) * 8;
            cp_async16(B + r * 136 + off, g_W1p + (size_t)(k0 + r) * C1 + n0 + off);
        }
        cp_commit();
    };

    issue(0, 0);
    issue(1, 1);
    issue(2, 2);

    for (int kt = 0; kt < 8; ++kt) {
        const int s = kt % 3;
        if (kt < 6) cp_wait<2>(); else if (kt == 6) cp_wait<1>(); else cp_wait<0>();
        __syncthreads();

        const __half* A = reinterpret_cast<const __half*>(smbuf + s * G1_STAGE);
        const __half* B = A + 9216;
#pragma unroll
        for (int kk = 0; kk < 4; ++kk) {
            wmma::fragment<wmma::matrix_a, 16, 16, 16, __half, wmma::row_major> af[2];
            wmma::fragment<wmma::matrix_b, 16, 16, 16, __half, wmma::row_major> bf[4];
#pragma unroll
            for (int i = 0; i < 2; ++i)
                wmma::load_matrix_sync(af[i], A + (wm * 32 + i * 16) * 72 + kk * 16, 72);
#pragma unroll
            for (int j = 0; j < 4; ++j)
                wmma::load_matrix_sync(bf[j], B + (kk * 16) * 136 + wn * 64 + j * 16, 136);
#pragma unroll
            for (int i = 0; i < 2; ++i)
#pragma unroll
                for (int j = 0; j < 4; ++j)
                    wmma::mma_sync(acc[i][j], af[i], bf[j], acc[i][j]);
        }
        __syncthreads();
        if (kt + 3 < 8) issue(kt + 3, s);
    }

    // ---- epilogue: C -> smem, fused BN1 stats atomics, fp16 h1 store ----
    __syncthreads();
    float* Cs = reinterpret_cast<float*>(smbuf);   // [128][132]
#pragma unroll
    for (int i = 0; i < 2; ++i)
#pragma unroll
        for (int j = 0; j < 4; ++j)
            wmma::store_matrix_sync(Cs + (wm * 32 + i * 16) * 132 + wn * 64 + j * 16,
                                    acc[i][j], 132, wmma::mem_row_major);
    __syncthreads();

    {
        int c = tid & 127, hf = tid >> 7;
        float s = 0.f, q = 0.f;
#pragma unroll 8
        for (int r = hf * 64; r < hf * 64 + 64; ++r) {
            float v = Cs[r * 132 + c];
            s += v;
            q = fmaf(v, v, q);
        }
        atomicAdd(&g_sum1[n0 + c], s);
        atomicAdd(&g_ssq1[n0 + c], q);
    }

#pragma unroll
    for (int i = 0; i < 32; ++i) {
        int pid = tid + i * 256;
        int r = pid >> 6, c2 = pid & 63;
        __half2 h = __floats2half2_rn(Cs[r * 132 + 2 * c2], Cs[r * 132 + 2 * c2 + 1]);
        *reinterpret_cast<__half2*>(g_h1 + (m0 + r) * C1 + n0 + 2 * c2) = h;
    }
}

// ---------------- 3: GEMM2 (PROFILED) — half2 BN, load/BN overlap ----------------
#define G2_A_BYTES (128 * 136 * 2)   // 34816
#define G2_B_BYTES (128 * 72 * 2)    // 18432
#define G2_SMEM (G2_A_BYTES + G2_B_BYTES + 128 * 2 * 2)  // 53760

__global__ void __launch_bounds__(256) gemm2_kernel(float invN) {
    extern __shared__ char smbuf[];
    const int e = blockIdx.x;
    const size_t m0 = (size_t)blockIdx.y * 128;
    const int tid = threadIdx.x;

    __half* A = reinterpret_cast<__half*>(smbuf);                 // [128][136]
    __half* B = reinterpret_cast<__half*>(smbuf + G2_A_BYTES);    // [128][72]
    __half* msh = reinterpret_cast<__half*>(smbuf + G2_A_BYTES + G2_B_BYTES);  // [128]
    __half* ish = msh + 128;                                                   // [128]

    // group 0: A rows 0..63
#pragma unroll
    for (int i = 0; i < 4; ++i) {
        int c = tid + i * 256;                  // 0..1023
        int r = c >> 4, col = (c & 15) * 8;
        cp_async16(A + r * 136 + col, g_h1 + (m0 + r) * C1 + e * H1 + col);
    }
    cp_commit();
    // group 1: A rows 64..127 + B
#pragma unroll
    for (int i = 0; i < 4; ++i) {
        int c = tid + i * 256;
        int r = (c >> 4) + 64, col = (c & 15) * 8;
        cp_async16(A + r * 136 + col, g_h1 + (m0 + r) * C1 + e * H1 + col);
    }
#pragma unroll
    for (int i = 0; i < 4; ++i) {
        int c = tid + i * 256;
        int r = c >> 3, col = (c & 7) * 8;
        cp_async16(B + r * 72 + col, g_W2h + (size_t)e * (H1 * H2) + r * H2 + col);
    }
    cp_commit();

    // inline BN1 finalize from raw sums -> fp16 tables (overlaps loads)
    if (tid < 128) {
        float m = g_sum1[e * H1 + tid] * invN;
        float q = g_ssq1[e * H1 + tid] * invN;
        msh[tid] = __float2half_rn(m);
        ish[tid] = __float2half_rn(rsqrtf(fmaxf(q - m * m, 0.f) + 1e-4f));
    }

    const __half2 z2 = __float2half2_rn(0.f);
    const __half2 k2 = __float2half2_rn(0.01f);
    auto bn_half = [&](int h) {
#pragma unroll
        for (int i = 0; i < 16; ++i) {
            int pid = tid + i * 256;            // 0..4095 half2 pairs
            int r = (pid >> 6) + h * 64, c2 = pid & 63;
            __half2* p = reinterpret_cast<__half2*>(A + r * 136 + 2 * c2);
            __half2 v = *p;
            __half2 m2 = *reinterpret_cast<const __half2*>(msh + 2 * c2);
            __half2 i2 = *reinterpret_cast<const __half2*>(ish + 2 * c2);
            __half2 t = __hmul2(__hsub2(v, m2), i2);
            __half2 rlo = __hmul2(k2, __hmin2(t, z2));
            *p = __hadd2(__hmax2(t, z2), rlo);
        }
    };
    cp_wait<1>();
    __syncthreads();     // A half0 + stats visible
    bn_half(0);          // overlaps A half1 + B in flight
    cp_wait<0>();
    __syncthreads();
    bn_half(1);
    __syncthreads();

    const int warp = tid >> 5;
    const int wm = warp & 3;
    const int wn = warp >> 2;

    wmma::fragment<wmma::accumulator, 16, 16, 16, float> acc[2][2];
#pragma unroll
    for (int i = 0; i < 2; ++i)
#pragma unroll
        for (int j = 0; j < 2; ++j) wmma::fill_fragment(acc[i][j], 0.0f);

#pragma unroll
    for (int kk = 0; kk < 8; ++kk) {
        wmma::fragment<wmma::matrix_a, 16, 16, 16, __half, wmma::row_major> af[2];
        wmma::fragment<wmma::matrix_b, 16, 16, 16, __half, wmma::row_major> bf[2];
#pragma unroll
        for (int i = 0; i < 2; ++i)
            wmma::load_matrix_sync(af[i], A + (wm * 32 + i * 16) * 136 + kk * 16, 136);
#pragma unroll
        for (int j = 0; j < 2; ++j)
            wmma::load_matrix_sync(bf[j], B + (kk * 16) * 72 + wn * 32 + j * 16, 72);
#pragma unroll
        for (int i = 0; i < 2; ++i)
#pragma unroll
            for (int j = 0; j < 2; ++j)
                wmma::mma_sync(acc[i][j], af[i], bf[j], acc[i][j]);
    }

    __syncthreads();
    float* Cs = reinterpret_cast<float*>(smbuf);  // [128][68]
#pragma unroll
    for (int i = 0; i < 2; ++i)
#pragma unroll
        for (int j = 0; j < 2; ++j)
            wmma::store_matrix_sync(Cs + (wm * 32 + i * 16) * 68 + wn * 32 + j * 16,
                                    acc[i][j], 68, wmma::mem_row_major);
    __syncthreads();

    {
        int c = tid & 63, q4 = tid >> 6;
        float s = 0.f, q = 0.f;
#pragma unroll 8
        for (int r = q4 * 32; r < q4 * 32 + 32; ++r) {
            float v = Cs[r * 68 + c];
            s += v;
            q = fmaf(v, v, q);
        }
        atomicAdd(&g_sum2[e * H2 + c], s);
        atomicAdd(&g_ssq2[e * H2 + c], q);
    }

#pragma unroll
    for (int i = 0; i < 16; ++i) {
        int pid = tid + i * 256;
        int r = pid >> 5, c2 = pid & 31;
        __half2 h = __floats2half2_rn(Cs[r * 68 + 2 * c2], Cs[r * 68 + 2 * c2 + 1]);
        *reinterpret_cast<__half2*>(g_h2 + (m0 + r) * C2 + e * H2 + 2 * c2) = h;
    }
}

// ---------------- 4: final combine (512 threads, 256 rows/block) ----------------
__global__ void __launch_bounds__(512) final_kernel(const float* __restrict__ bs_p,
                                                    float* __restrict__ out, float invN) {
    __shared__ float m2s[C2], i2s[C2], vs[C2];   // 12 KB
    const int tid = threadIdx.x;
#pragma unroll
    for (int j = 0; j < 2; ++j) {
        int c = tid + j * 512;
        float m = g_sum2[c] * invN;
        float q = g_ssq2[c] * invN;
        m2s[c] = m;
        i2s[c] = rsqrtf(fmaxf(q - m * m, 0.f) + 1e-4f);
        vs[c] = g_v[c];
    }
    __syncthreads();

    const int e = tid & 15, rg = tid >> 4;   // rg 0..31
    const float bsv = bs_p[0];
    const float* mp = m2s + e * H2;
    const float* ip = i2s + e * H2;
    const float* vp = vs + e * H2;

#pragma unroll
    for (int jb = 0; jb < 8; ++jb) {
        const size_t row = (size_t)blockIdx.x * 256 + jb * 32 + rg;
        const uint4* hp = reinterpret_cast<const uint4*>(g_h2 + row * C2 + (size_t)e * H2);

        float acc = 0.f;
#pragma unroll
        for (int i = 0; i < 8; ++i) {
            uint4 q = hp[i];
            unsigned vals[4] = {q.x, q.y, q.z, q.w};
#pragma unroll
            for (int j = 0; j < 4; ++j) {
                __half2 h2 = *reinterpret_cast<__half2*>(&vals[j]);
                float2 f = __half22float2(h2);
                int k = i * 8 + j * 2;
                float a0 = (f.x - mp[k]) * ip[k];
                float a1 = (f.y - mp[k + 1]) * ip[k + 1];
                a0 = (a0 >= 0.f) ? a0 : 0.01f * a0;
                a1 = (a1 >= 0.f) ? a1 : 0.01f * a1;
                acc = fmaf(a0, vp[k], acc);
                acc = fmaf(a1, vp[k + 1], acc);
            }
        }
        float contrib = g_gate[row * E + e] * (acc + bsv);
#pragma unroll
        for (int o = 8; o; o >>= 1) contrib += __shfl_down_sync(0xffffffffu, contrib, o, 16);
        if (e == 0) out[row] = contrib;
    }
}

// ---------------- launch ----------------
extern "C" void kernel_launch(void* const* d_in, const int* in_sizes, int n_in,
                              void* d_out, int out_size) {
    const float* x  = (const float*)d_in[0];
    const float* Wg = (const float*)d_in[1];
    const float* bg = (const float*)d_in[2];
    const float* ga = (const float*)d_in[3];
    const float* be = (const float*)d_in[4];
    const float* W1 = (const float*)d_in[5];
    const float* W2 = (const float*)d_in[6];
    const float* W3 = (const float*)d_in[7];
    const float* Ws = (const float*)d_in[8];
    const float* bs = (const float*)d_in[9];
    float* out = (float*)d_out;

    const int N = in_sizes[0] / D;        // 65536
    const int mtiles = N / 128;           // 512
    const float invN = 1.0f / (float)N;

    static bool attr_done = false;
    if (!attr_done) {
        cudaFuncSetAttribute(gate_convert, cudaFuncAttributeMaxDynamicSharedMemorySize, GG_SMEM);
        cudaFuncSetAttribute(gemm1_kernel, cudaFuncAttributeMaxDynamicSharedMemorySize, G1_SMEM);
        cudaFuncSetAttribute(gemm2_kernel, cudaFuncAttributeMaxDynamicSharedMemorySize, G2_SMEM);
        attr_done = true;
    }

    pack_all<<<4096, 256>>>(W1, W2, W3, Ws, Wg);                  // 0
    gate_convert<<<mtiles, 256, GG_SMEM>>>(x, bg, ga, be);        // 1
    gemm1_kernel<<<dim3(C1 / 128, mtiles), 256, G1_SMEM>>>();     // 2
    gemm2_kernel<<<dim3(E, mtiles), 256, G2_SMEM>>>(invN);        // 3 (PROFILED)
    final_kernel<<<N / 256, 512>>>(bs, out, invN);                // 4
}

// round 17
// speedup vs baseline: 1.1799x; 1.1799x over previous
#include <cuda_runtime.h>
#include <cuda_fp16.h>
#include <mma.h>
#include <cstdint>

using namespace nvcuda;

#define D   512
#define E   16
#define H1  128
#define H2  64
#define R   32
#define C1  (E * H1)   // 2048
#define C2  (E * H2)   // 1024
#define NMAX 65536

// ---------------- scratch (device globals: allocation-free) ----------------
__device__ __half g_x16[(size_t)NMAX * D];        // 64 MB
__device__ __half g_W1p[(size_t)D * C1];          // 2 MB   [d][e*128+j]
__device__ __half g_W2h[(size_t)E * H1 * H2];     // 256 KB [e][k][j]
__device__ __half g_Wg16[D * E];                  // 16 KB  [d][e] fp16
__device__ __half g_h1[(size_t)NMAX * C1];        // 256 MB
__device__ __half g_h2[(size_t)NMAX * C2];        // 128 MB
__device__ float  g_gate[(size_t)NMAX * E];       // 4 MB
__device__ float  g_sum1[C1], g_ssq1[C1];
__device__ float  g_sum2[C2], g_ssq2[C2];
__device__ float  g_v[C2];

// ---------------- cp.async helpers ----------------
__device__ __forceinline__ void cp_async16(void* smem, const void* gmem) {
    unsigned int s = (unsigned int)__cvta_generic_to_shared(smem);
    asm volatile("cp.async.cg.shared.global [%0], [%1], 16;\n" :: "r"(s), "l"(gmem));
}
__device__ __forceinline__ void cp_commit() {
    asm volatile("cp.async.commit_group;\n");
}
template <int NN>
__device__ __forceinline__ void cp_wait() {
    asm volatile("cp.async.wait_group %0;\n" :: "n"(NN));
}

// ---------------- 0: pack all weights + zero stats ----------------
__global__ void __launch_bounds__(256) pack_all(const float* __restrict__ W1,
                                                const float* __restrict__ W2,
                                                const float* __restrict__ W3,
                                                const float* __restrict__ Ws,
                                                const float* __restrict__ Wg) {
    int idx = blockIdx.x * 256 + threadIdx.x;   // grid 4096 -> 1048576
    if (idx < E * D * H1) {
        int j = idx & (H1 - 1);
        int d = (idx >> 7) & (D - 1);
        int e = idx >> 16;
        g_W1p[(size_t)d * C1 + e * H1 + j] = __float2half_rn(W1[idx]);
    }
    if (idx < E * H1 * H2) g_W2h[idx] = __float2half_rn(W2[idx]);
    if (idx < D * E) g_Wg16[idx] = __float2half_rn(Wg[idx]);
    if (idx < C2) {
        float v = 0.f;
#pragma unroll
        for (int r = 0; r < R; ++r) v = fmaf(W3[(size_t)idx * R + r], Ws[r], v);
        g_v[idx] = v;
        g_sum2[idx] = 0.f; g_ssq2[idx] = 0.f;
    }
    if (idx < C1) { g_sum1[idx] = 0.f; g_ssq1[idx] = 0.f; }
}

// ---------------- 1: fused convert x->fp16 + gating GEMM + LN + softmax ----------------
#define GG_WG   16384
#define GG_STG  18432
#define GG_SMEM (GG_WG + 2 * GG_STG)   // 53248

__global__ void __launch_bounds__(256) gate_convert(const float* __restrict__ x,
                                                    const float* __restrict__ bg,
                                                    const float* __restrict__ gamma_,
                                                    const float* __restrict__ beta_) {
    extern __shared__ char smg[];
    __half* Wgs = reinterpret_cast<__half*>(smg);
    const size_t m0 = (size_t)blockIdx.x * 128;
    const int tid = threadIdx.x;
    const int warp = tid >> 5;

#pragma unroll
    for (int i = 0; i < 4; ++i) {
        int c = tid + i * 256;
        cp_async16(Wgs + c * 8, g_Wg16 + c * 8);
    }
    cp_commit();

    float4 reg[8];
    auto preload = [&](int kt) {
#pragma unroll
        for (int i = 0; i < 8; ++i) {
            int c = tid + i * 256;
            int r = c >> 4, c4 = c & 15;
            reg[i] = *reinterpret_cast<const float4*>(
                x + (m0 + r) * D + kt * 64 + c4 * 4);
        }
    };
    auto store_stage = [&](int s, int kt) {
        __half* A = reinterpret_cast<__half*>(smg + GG_WG + s * GG_STG);
#pragma unroll
        for (int i = 0; i < 8; ++i) {
            int c = tid + i * 256;
            int r = c >> 4, c4 = c & 15;
            __half2 h0 = __floats2half2_rn(reg[i].x, reg[i].y);
            __half2 h1 = __floats2half2_rn(reg[i].z, reg[i].w);
            uint2 u = make_uint2(*reinterpret_cast<unsigned*>(&h0),
                                 *reinterpret_cast<unsigned*>(&h1));
            *reinterpret_cast<uint2*>(A + r * 72 + c4 * 4) = u;
            *reinterpret_cast<uint2*>(g_x16 + (m0 + r) * D + kt * 64 + c4 * 4) = u;
        }
    };

    wmma::fragment<wmma::accumulator, 16, 16, 16, float> acc;
    wmma::fill_fragment(acc, 0.0f);

    preload(0);
    for (int kt = 0; kt < 8; ++kt) {
        const int s = kt & 1;
        store_stage(s, kt);
        if (kt < 7) preload(kt + 1);
        if (kt == 0) cp_wait<0>();
        __syncthreads();

        const __half* A = reinterpret_cast<const __half*>(smg + GG_WG + s * GG_STG);
#pragma unroll
        for (int kk = 0; kk < 4; ++kk) {
            wmma::fragment<wmma::matrix_a, 16, 16, 16, __half, wmma::row_major> af;
            wmma::fragment<wmma::matrix_b, 16, 16, 16, __half, wmma::row_major> bf;
            wmma::load_matrix_sync(af, A + (warp * 16) * 72 + kk * 16, 72);
            wmma::load_matrix_sync(bf, Wgs + (kt * 64 + kk * 16) * E, E);
            wmma::mma_sync(acc, af, bf, acc);
        }
    }

    float* gsm = reinterpret_cast<float*>(smg + GG_WG);
    wmma::store_matrix_sync(gsm + warp * 16 * 20, acc, 20, wmma::mem_row_major);
    __syncthreads();

    if (tid < 128) {
        float g[E];
        float mu = 0.f;
#pragma unroll
        for (int e = 0; e < E; ++e) {
            g[e] = gsm[tid * 20 + e] + bg[e];
            mu += g[e];
        }
        mu *= (1.f / 16.f);
        float vv = 0.f;
#pragma unroll
        for (int e = 0; e < E; ++e) {
            g[e] -= mu;
            vv = fmaf(g[e], g[e], vv);
        }
        float rstd = rsqrtf(vv * (1.f / 16.f) + 1e-5f);
        float mx = -1e30f;
#pragma unroll
        for (int e = 0; e < E; ++e) {
            g[e] = g[e] * rstd * gamma_[e] + beta_[e];
            mx = fmaxf(mx, g[e]);
        }
        float es = 0.f;
#pragma unroll
        for (int e = 0; e < E; ++e) {
            g[e] = __expf(g[e] - mx);
            es += g[e];
        }
        float inv = 1.f / es;
        float4* gp = reinterpret_cast<float4*>(g_gate + (m0 + tid) * E);
#pragma unroll
        for (int q = 0; q < 4; ++q)
            gp[q] = make_float4(g[4 * q] * inv, g[4 * q + 1] * inv,
                                g[4 * q + 2] * inv, g[4 * q + 3] * inv);
    }
}

// ---------------- 2: GEMM1 h1 = x16 @ W1p (R9 mainloop, frozen at 450us) ----------------
#define G1_STAGE 35840
#define G1_SMEM  (3 * G1_STAGE)   // 107520

__global__ void __launch_bounds__(256) gemm1_kernel() {
    extern __shared__ char smbuf[];
    const int n0 = blockIdx.x * 128;
    const size_t m0 = (size_t)blockIdx.y * 128;
    const int tid = threadIdx.x;
    const int warp = tid >> 5;
    const int wm = warp & 3;    // 4 warps over M
    const int wn = warp >> 2;   // 2 warps over N

    wmma::fragment<wmma::accumulator, 16, 16, 16, float> acc[2][4];
#pragma unroll
    for (int i = 0; i < 2; ++i)
#pragma unroll
        for (int j = 0; j < 4; ++j) wmma::fill_fragment(acc[i][j], 0.0f);

    auto issue = [&](int kt, int s) {
        const int k0 = kt * 64;
        __half* A = reinterpret_cast<__half*>(smbuf + s * G1_STAGE);
        __half* B = A + 9216;   // 128*72 halves
#pragma unroll
        for (int i = 0; i < 4; ++i) {
            int c = tid + i * 256;            // 0..1023
            int r = c >> 3, off = (c & 7) * 8;
            cp_async16(A + r * 72 + off, g_x16 + (m0 + r) * D + k0 + off);
        }
#pragma unroll
        for (int i = 0; i < 4; ++i) {
            int c = tid + i * 256;
            int r = c >> 4, off = (c & 15) * 8;
            cp_async16(B + r * 136 + off, g_W1p + (size_t)(k0 + r) * C1 + n0 + off);
        }
        cp_commit();
    };

    issue(0, 0);
    issue(1, 1);
    issue(2, 2);

    for (int kt = 0; kt < 8; ++kt) {
        const int s = kt % 3;
        if (kt < 6) cp_wait<2>(); else if (kt == 6) cp_wait<1>(); else cp_wait<0>();
        __syncthreads();

        const __half* A = reinterpret_cast<const __half*>(smbuf + s * G1_STAGE);
        const __half* B = A + 9216;
#pragma unroll
        for (int kk = 0; kk < 4; ++kk) {
            wmma::fragment<wmma::matrix_a, 16, 16, 16, __half, wmma::row_major> af[2];
            wmma::fragment<wmma::matrix_b, 16, 16, 16, __half, wmma::row_major> bf[4];
#pragma unroll
            for (int i = 0; i < 2; ++i)
                wmma::load_matrix_sync(af[i], A + (wm * 32 + i * 16) * 72 + kk * 16, 72);
#pragma unroll
            for (int j = 0; j < 4; ++j)
                wmma::load_matrix_sync(bf[j], B + (kk * 16) * 136 + wn * 64 + j * 16, 136);
#pragma unroll
            for (int i = 0; i < 2; ++i)
#pragma unroll
                for (int j = 0; j < 4; ++j)
                    wmma::mma_sync(acc[i][j], af[i], bf[j], acc[i][j]);
        }
        __syncthreads();
        if (kt + 3 < 8) issue(kt + 3, s);
    }

    // ---- epilogue: C -> smem, fused BN1 stats atomics, fp16 h1 store ----
    __syncthreads();
    float* Cs = reinterpret_cast<float*>(smbuf);   // [128][132]
#pragma unroll
    for (int i = 0; i < 2; ++i)
#pragma unroll
        for (int j = 0; j < 4; ++j)
            wmma::store_matrix_sync(Cs + (wm * 32 + i * 16) * 132 + wn * 64 + j * 16,
                                    acc[i][j], 132, wmma::mem_row_major);
    __syncthreads();

    {
        int c = tid & 127, hf = tid >> 7;
        float s = 0.f, q = 0.f;
#pragma unroll 8
        for (int r = hf * 64; r < hf * 64 + 64; ++r) {
            float v = Cs[r * 132 + c];
            s += v;
            q = fmaf(v, v, q);
        }
        atomicAdd(&g_sum1[n0 + c], s);
        atomicAdd(&g_ssq1[n0 + c], q);
    }

#pragma unroll
    for (int i = 0; i < 32; ++i) {
        int pid = tid + i * 256;
        int r = pid >> 6, c2 = pid & 63;
        __half2 h = __floats2half2_rn(Cs[r * 132 + 2 * c2], Cs[r * 132 + 2 * c2 + 1]);
        *reinterpret_cast<__half2*>(g_h1 + (m0 + r) * C1 + n0 + 2 * c2) = h;
    }
}

// ---------------- 3: GEMM2 (PROFILED) — half2 BN, load/BN overlap ----------------
#define G2_A_BYTES (128 * 136 * 2)   // 34816
#define G2_B_BYTES (128 * 72 * 2)    // 18432
#define G2_SMEM (G2_A_BYTES + G2_B_BYTES + 128 * 2 * 2)  // 53760

__global__ void __launch_bounds__(256) gemm2_kernel(float invN) {
    extern __shared__ char smbuf[];
    const int e = blockIdx.x;
    const size_t m0 = (size_t)blockIdx.y * 128;
    const int tid = threadIdx.x;

    __half* A = reinterpret_cast<__half*>(smbuf);                 // [128][136]
    __half* B = reinterpret_cast<__half*>(smbuf + G2_A_BYTES);    // [128][72]
    __half* msh = reinterpret_cast<__half*>(smbuf + G2_A_BYTES + G2_B_BYTES);  // [128]
    __half* ish = msh + 128;                                                   // [128]

    // group 0: A rows 0..63
#pragma unroll
    for (int i = 0; i < 4; ++i) {
        int c = tid + i * 256;                  // 0..1023
        int r = c >> 4, col = (c & 15) * 8;
        cp_async16(A + r * 136 + col, g_h1 + (m0 + r) * C1 + e * H1 + col);
    }
    cp_commit();
    // group 1: A rows 64..127 + B
#pragma unroll
    for (int i = 0; i < 4; ++i) {
        int c = tid + i * 256;
        int r = (c >> 4) + 64, col = (c & 15) * 8;
        cp_async16(A + r * 136 + col, g_h1 + (m0 + r) * C1 + e * H1 + col);
    }
#pragma unroll
    for (int i = 0; i < 4; ++i) {
        int c = tid + i * 256;
        int r = c >> 3, col = (c & 7) * 8;
        cp_async16(B + r * 72 + col, g_W2h + (size_t)e * (H1 * H2) + r * H2 + col);
    }
    cp_commit();

    // inline BN1 finalize from raw sums -> fp16 tables (overlaps loads)
    if (tid < 128) {
        float m = g_sum1[e * H1 + tid] * invN;
        float q = g_ssq1[e * H1 + tid] * invN;
        msh[tid] = __float2half_rn(m);
        ish[tid] = __float2half_rn(rsqrtf(fmaxf(q - m * m, 0.f) + 1e-4f));
    }

    const __half2 z2 = __float2half2_rn(0.f);
    const __half2 k2 = __float2half2_rn(0.01f);
    auto bn_half = [&](int h) {
#pragma unroll
        for (int i = 0; i < 16; ++i) {
            int pid = tid + i * 256;            // 0..4095 half2 pairs
            int r = (pid >> 6) + h * 64, c2 = pid & 63;
            __half2* p = reinterpret_cast<__half2*>(A + r * 136 + 2 * c2);
            __half2 v = *p;
            __half2 m2 = *reinterpret_cast<const __half2*>(msh + 2 * c2);
            __half2 i2 = *reinterpret_cast<const __half2*>(ish + 2 * c2);
            __half2 t = __hmul2(__hsub2(v, m2), i2);
            __half2 rlo = __hmul2(k2, __hmin2(t, z2));
            *p = __hadd2(__hmax2(t, z2), rlo);
        }
    };
    cp_wait<1>();
    __syncthreads();     // A half0 + stats visible
    bn_half(0);          // overlaps A half1 + B in flight
    cp_wait<0>();
    __syncthreads();
    bn_half(1);
    __syncthreads();

    const int warp = tid >> 5;
    const int wm = warp & 3;
    const int wn = warp >> 2;

    wmma::fragment<wmma::accumulator, 16, 16, 16, float> acc[2][2];
#pragma unroll
    for (int i = 0; i < 2; ++i)
#pragma unroll
        for (int j = 0; j < 2; ++j) wmma::fill_fragment(acc[i][j], 0.0f);

#pragma unroll
    for (int kk = 0; kk < 8; ++kk) {
        wmma::fragment<wmma::matrix_a, 16, 16, 16, __half, wmma::row_major> af[2];
        wmma::fragment<wmma::matrix_b, 16, 16, 16, __half, wmma::row_major> bf[2];
#pragma unroll
        for (int i = 0; i < 2; ++i)
            wmma::load_matrix_sync(af[i], A + (wm * 32 + i * 16) * 136 + kk * 16, 136);
#pragma unroll
        for (int j = 0; j < 2; ++j)
            wmma::load_matrix_sync(bf[j], B + (kk * 16) * 72 + wn * 32 + j * 16, 72);
#pragma unroll
        for (int i = 0; i < 2; ++i)
#pragma unroll
            for (int j = 0; j < 2; ++j)
                wmma::mma_sync(acc[i][j], af[i], bf[j], acc[i][j]);
    }

    __syncthreads();
    float* Cs = reinterpret_cast<float*>(smbuf);  // [128][68]
#pragma unroll
    for (int i = 0; i < 2; ++i)
#pragma unroll
        for (int j = 0; j < 2; ++j)
            wmma::store_matrix_sync(Cs + (wm * 32 + i * 16) * 68 + wn * 32 + j * 16,
                                    acc[i][j], 68, wmma::mem_row_major);
    __syncthreads();

    {
        int c = tid & 63, q4 = tid >> 6;
        float s = 0.f, q = 0.f;
#pragma unroll 8
        for (int r = q4 * 32; r < q4 * 32 + 32; ++r) {
            float v = Cs[r * 68 + c];
            s += v;
            q = fmaf(v, v, q);
        }
        atomicAdd(&g_sum2[e * H2 + c], s);
        atomicAdd(&g_ssq2[e * H2 + c], q);
    }

#pragma unroll
    for (int i = 0; i < 16; ++i) {
        int pid = tid + i * 256;
        int r = pid >> 5, c2 = pid & 31;
        __half2 h = __floats2half2_rn(Cs[r * 68 + 2 * c2], Cs[r * 68 + 2 * c2 + 1]);
        *reinterpret_cast<__half2*>(g_h2 + (m0 + r) * C2 + e * H2 + 2 * c2) = h;
    }
}

// ---------------- 4: final combine (R15 version: 256 threads, 256 rows/block) ----------------
__global__ void __launch_bounds__(256) final_kernel(const float* __restrict__ bs_p,
                                                    float* __restrict__ out, float invN) {
    __shared__ float m2s[C2], i2s[C2], vs[C2];   // 12 KB
    const int tid = threadIdx.x;
#pragma unroll
    for (int j = 0; j < 4; ++j) {
        int c = tid + j * 256;
        float m = g_sum2[c] * invN;
        float q = g_ssq2[c] * invN;
        m2s[c] = m;
        i2s[c] = rsqrtf(fmaxf(q - m * m, 0.f) + 1e-4f);
        vs[c] = g_v[c];
    }
    __syncthreads();

    const int e = tid & 15, r = tid >> 4;
    const float bsv = bs_p[0];
    const float* mp = m2s + e * H2;
    const float* ip = i2s + e * H2;
    const float* vp = vs + e * H2;

#pragma unroll
    for (int jb = 0; jb < 16; ++jb) {
        const size_t row = (size_t)blockIdx.x * 256 + jb * 16 + r;
        const uint4* hp = reinterpret_cast<const uint4*>(g_h2 + row * C2 + (size_t)e * H2);

        float acc = 0.f;
#pragma unroll
        for (int i = 0; i < 8; ++i) {
            uint4 q = hp[i];
            unsigned vals[4] = {q.x, q.y, q.z, q.w};
#pragma unroll
            for (int j = 0; j < 4; ++j) {
                __half2 h2 = *reinterpret_cast<__half2*>(&vals[j]);
                float2 f = __half22float2(h2);
                int k = i * 8 + j * 2;
                float a0 = (f.x - mp[k]) * ip[k];
                float a1 = (f.y - mp[k + 1]) * ip[k + 1];
                a0 = (a0 >= 0.f) ? a0 : 0.01f * a0;
                a1 = (a1 >= 0.f) ? a1 : 0.01f * a1;
                acc = fmaf(a0, vp[k], acc);
                acc = fmaf(a1, vp[k + 1], acc);
            }
        }
        float contrib = g_gate[row * E + e] * (acc + bsv);
#pragma unroll
        for (int o = 8; o; o >>= 1) contrib += __shfl_down_sync(0xffffffffu, contrib, o, 16);
        if (e == 0) out[row] = contrib;
    }
}

// ---------------- launch ----------------
extern "C" void kernel_launch(void* const* d_in, const int* in_sizes, int n_in,
                              void* d_out, int out_size) {
    const float* x  = (const float*)d_in[0];
    const float* Wg = (const float*)d_in[1];
    const float* bg = (const float*)d_in[2];
    const float* ga = (const float*)d_in[3];
    const float* be = (const float*)d_in[4];
    const float* W1 = (const float*)d_in[5];
    const float* W2 = (const float*)d_in[6];
    const float* W3 = (const float*)d_in[7];
    const float* Ws = (const float*)d_in[8];
    const float* bs = (const float*)d_in[9];
    float* out = (float*)d_out;

    const int N = in_sizes[0] / D;        // 65536
    const int mtiles = N / 128;           // 512
    const float invN = 1.0f / (float)N;

    static bool attr_done = false;
    if (!attr_done) {
        cudaFuncSetAttribute(gate_convert, cudaFuncAttributeMaxDynamicSharedMemorySize, GG_SMEM);
        cudaFuncSetAttribute(gemm1_kernel, cudaFuncAttributeMaxDynamicSharedMemorySize, G1_SMEM);
        cudaFuncSetAttribute(gemm2_kernel, cudaFuncAttributeMaxDynamicSharedMemorySize, G2_SMEM);
        attr_done = true;
    }

    pack_all<<<4096, 256>>>(W1, W2, W3, Ws, Wg);                  // 0
    gate_convert<<<mtiles, 256, GG_SMEM>>>(x, bg, ga, be);        // 1
    gemm1_kernel<<<dim3(C1 / 128, mtiles), 256, G1_SMEM>>>();     // 2
    gemm2_kernel<<<dim3(E, mtiles), 256, G2_SMEM>>>(invN);        // 3 (PROFILED)
    final_kernel<<<N / 256, 256>>>(bs, out, invN);                // 4
}